// round 11
// baseline (speedup 1.0000x reference)
#include <cuda_runtime.h>
#include <cuda_fp16.h>

// DynamicDilationUnfold R11: R10 + 4-output-row blocks (512 thr, 10-row halo)
// to cut fill redundancy 4x -> 2.5x. Streaming stores, uint4 smem packing,
// k=0 integer-tap specialization. B=4, C=64, H=W=128, G=4, Cg=16, K=3.

#define B_    4
#define C_    64
#define H_    128
#define W_    128
#define G_    4
#define CG_   16
#define HW_   (H_ * W_)          // 16384
#define NC8   2                  // channel octets per group (16/8)
#define NROWS 10                 // rows hb-1 .. hb+8 (4 out rows, d < 3.0)
#define WP    (W_ + 1)           // padded row (bank stagger)
#define TT    9                  // taps per channel
#define CS    (TT * HW_)         // out channel stride (elements)
#define NTHR  512

__device__ __forceinline__ __half2 u2h(unsigned int u) {
    return *reinterpret_cast<__half2*>(&u);
}
__device__ __forceinline__ unsigned int h2u(__half2 h) {
    return *reinterpret_cast<unsigned int*>(&h);
}
__device__ __forceinline__ __half2 lerpu(__half2 w0, __half2 w1,
                                         unsigned int a, unsigned int b) {
    return __hfma2(w1, u2h(b), __hmul2(w0, u2h(a)));
}
__device__ __forceinline__ __half2 lerph(__half2 w0, __half2 w1,
                                         __half2 a, __half2 b) {
    return __hfma2(w1, b, __hmul2(w0, a));
}

// store 8 channels (4 half2) of one tap — streaming (evict-first)
__device__ __forceinline__ void st8(float* __restrict__ o, int tap,
                                    __half2 a, __half2 b, __half2 c, __half2 e)
{
    float* p = o + (size_t)tap * HW_;
    float2 f;
    f = __half22float2(a); __stcs(p,             f.x); __stcs(p + 1u * CS, f.y);
    f = __half22float2(b); __stcs(p + 2u * CS, f.x); __stcs(p + 3u * CS, f.y);
    f = __half22float2(c); __stcs(p + 4u * CS, f.x); __stcs(p + 5u * CS, f.y);
    f = __half22float2(e); __stcs(p + 6u * CS, f.x); __stcs(p + 7u * CS, f.y);
}

__global__ __launch_bounds__(NTHR, 2)
void ddunfold_kernel(const float* __restrict__ x,
                     const float* __restrict__ dmap,
                     float* __restrict__ out)
{
    __shared__ uint4 tile[NC8][NROWS][WP];   // 2*10*129*16 = 41,280 B

    const int wo = threadIdx.x & (W_ - 1);   // 0..127
    const int ty = threadIdx.x >> 7;         // 0..3: which output row
    const int hb = blockIdx.x << 2;          // ho base (multiple of 4)
    const int g  = blockIdx.y;               // 0..3
    const int b  = blockIdx.z;               // 0..3

    const int ho = hb + ty;
    const float d = dmap[((b * G_ + g) * H_ + ho) * W_ + wo];  // early load

    // ---- fused fill: fp32 planar -> half8 (uint4) packed smem rows ----
    // 2 c8-planes x 10 rows x 128 wo = 2560 units / 512 thr = 5 exact iters
    const float* __restrict__ xg = x + (size_t)(b * C_ + g * CG_) * HW_;
    #pragma unroll
    for (int i = 0; i < 5; i++) {
        const int u   = threadIdx.x + i * NTHR;   // 0..2559
        const int wf  = u & (W_ - 1);
        const int rp  = u >> 7;                   // 0..19
        const int c8  = rp / NROWS;               // 0..1
        const int j   = rp - c8 * NROWS;          // 0..9
        const int gr  = min(max(hb - 1 + j, 0), H_ - 1);
        const float* xp = xg + (size_t)(c8 * 8) * HW_ + gr * W_ + wf;
        uint4 v;
        v.x = h2u(__floats2half2_rn(__ldg(xp),           __ldg(xp + HW_)));
        v.y = h2u(__floats2half2_rn(__ldg(xp + 2 * HW_), __ldg(xp + 3 * HW_)));
        v.z = h2u(__floats2half2_rn(__ldg(xp + 4 * HW_), __ldg(xp + 5 * HW_)));
        v.w = h2u(__floats2half2_rn(__ldg(xp + 6 * HW_), __ldg(xp + 7 * HW_)));
        tile[c8][j][wf] = v;
    }

    // ---- k=0: exact integer tap at (ho-1, wo-1) ----
    const __half2 mh0 = __float2half2_rn(ho >= 1 ? 1.0f : 0.0f);
    const __half2 mw0 = __float2half2_rn(wo >= 1 ? 1.0f : 0.0f);
    const __half2 m00 = __hmul2(mh0, mw0);
    const int wm1 = max(wo - 1, 0);

    // ---- k=1,2: separable weights + smem indices ----
    __half2 ah0h[2], ah1h[2], bw0h[2], bw1h[2];
    int jh0[2], jh1[2], w0c[2], w1c[2];

    #pragma unroll
    for (int kk = 0; kk < 2; kk++) {
        const float kf = (float)(kk + 1);
        { // h axis
            const float p  = (float)(ho - 1) + kf * d;
            const float f0 = floorf(p);
            const float l  = p - f0;
            const bool  v0 = (f0 >= 0.0f)  && (f0 <= (float)(H_ - 1));
            const bool  v1 = (f0 >= -1.0f) && (f0 <= (float)(H_ - 2));
            ah0h[kk] = __float2half2_rn(v0 ? (1.0f - l) : 0.0f);
            ah1h[kk] = __float2half2_rn(v1 ? l : 0.0f);
            const int j = (int)f0 - (hb - 1);     // 0..8 nominal (row tile idx)
            jh0[kk] = min(max(j,     0), NROWS - 1);
            jh1[kk] = min(max(j + 1, 0), NROWS - 1);
        }
        { // w axis
            const float p  = (float)(wo - 1) + kf * d;
            const float f0 = floorf(p);
            const float l  = p - f0;
            const bool  v0 = (f0 >= 0.0f)  && (f0 <= (float)(W_ - 1));
            const bool  v1 = (f0 >= -1.0f) && (f0 <= (float)(W_ - 2));
            bw0h[kk] = __float2half2_rn(v0 ? (1.0f - l) : 0.0f);
            bw1h[kk] = __float2half2_rn(v1 ? l : 0.0f);
            const int i0 = (int)f0;
            w0c[kk] = min(max(i0,     0), W_ - 1);
            w1c[kk] = min(max(i0 + 1, 0), W_ - 1);
        }
    }

    __syncthreads();

    const int pix = ho * W_ + wo;
    const int ty1 = ty + 1;                   // smem row of output row ho
    float* __restrict__ ob = out + ((size_t)(b * C_ + g * CG_)) * CS + pix;

    #pragma unroll
    for (int c8 = 0; c8 < NC8; c8++) {
        float* __restrict__ oc = ob + (size_t)(c8 * 8) * CS;

        // tap (0,0): direct copy with border mask (row ho-1 = tile row ty)
        {
            const uint4 q = tile[c8][ty][wm1];
            st8(oc, 0,
                __hmul2(m00, u2h(q.x)), __hmul2(m00, u2h(q.y)),
                __hmul2(m00, u2h(q.z)), __hmul2(m00, u2h(q.w)));
        }

        // taps (0,kw), kw=1,2: horizontal lerp on row ho-1 (mask mh0)
        #pragma unroll
        for (int kk = 0; kk < 2; kk++) {
            const uint4 q0 = tile[c8][ty][w0c[kk]];
            const uint4 q1 = tile[c8][ty][w1c[kk]];
            const __half2 wa = __hmul2(mh0, bw0h[kk]);
            const __half2 wb = __hmul2(mh0, bw1h[kk]);
            st8(oc, kk + 1,
                lerpu(wa, wb, q0.x, q1.x), lerpu(wa, wb, q0.y, q1.y),
                lerpu(wa, wb, q0.z, q1.z), lerpu(wa, wb, q0.w, q1.w));
        }

        // taps (kh,0), kh=1,2: vertical lerp on col wo-1 (mask mw0)
        #pragma unroll
        for (int kk = 0; kk < 2; kk++) {
            const uint4 q0 = tile[c8][jh0[kk]][wm1];
            const uint4 q1 = tile[c8][jh1[kk]][wm1];
            const __half2 wa = __hmul2(mw0, ah0h[kk]);
            const __half2 wb = __hmul2(mw0, ah1h[kk]);
            st8(oc, (kk + 1) * 3,
                lerpu(wa, wb, q0.x, q1.x), lerpu(wa, wb, q0.y, q1.y),
                lerpu(wa, wb, q0.z, q1.z), lerpu(wa, wb, q0.w, q1.w));
        }

        // full bilinear taps (kh,kw), kh,kw in {1,2}
        #pragma unroll
        for (int kh = 0; kh < 2; kh++) {
            const int r0 = jh0[kh];
            const int r1 = jh1[kh];
            #pragma unroll
            for (int kw = 0; kw < 2; kw++) {
                const uint4 q00 = tile[c8][r0][w0c[kw]];
                const uint4 q01 = tile[c8][r0][w1c[kw]];
                const uint4 q10 = tile[c8][r1][w0c[kw]];
                const uint4 q11 = tile[c8][r1][w1c[kw]];

                const __half2 ox = lerph(ah0h[kh], ah1h[kh],
                                         lerpu(bw0h[kw], bw1h[kw], q00.x, q01.x),
                                         lerpu(bw0h[kw], bw1h[kw], q10.x, q11.x));
                const __half2 oy = lerph(ah0h[kh], ah1h[kh],
                                         lerpu(bw0h[kw], bw1h[kw], q00.y, q01.y),
                                         lerpu(bw0h[kw], bw1h[kw], q10.y, q11.y));
                const __half2 oz = lerph(ah0h[kh], ah1h[kh],
                                         lerpu(bw0h[kw], bw1h[kw], q00.z, q01.z),
                                         lerpu(bw0h[kw], bw1h[kw], q10.z, q11.z));
                const __half2 ow = lerph(ah0h[kh], ah1h[kh],
                                         lerpu(bw0h[kw], bw1h[kw], q00.w, q01.w),
                                         lerpu(bw0h[kw], bw1h[kw], q10.w, q11.w));

                st8(oc, (kh + 1) * 3 + (kw + 1), ox, oy, oz, ow);
            }
        }
    }
    (void)ty1;
}

extern "C" void kernel_launch(void* const* d_in, const int* in_sizes, int n_in,
                              void* d_out, int out_size)
{
    const float* x    = (const float*)d_in[0];
    const float* dmap = (const float*)d_in[1];
    float* out        = (float*)d_out;

    dim3 grid(H_ / 4, G_, B_);   // (4-row tile, g, b)
    dim3 block(NTHR);            // 4 rows x 128 wo
    ddunfold_kernel<<<grid, block>>>(x, dmap, out);
}

// round 12
// speedup vs baseline: 1.0789x; 1.0789x over previous
#include <cuda_runtime.h>
#include <cuda_fp16.h>

// DynamicDilationUnfold R12: R10 (best: 27.1us) + float2-vectorized smem fill.
// 2-row tiles, 256 thr, 4 blocks/SM, streaming stores, uint4 smem packing,
// k=0 integer-tap specialization. B=4, C=64, H=W=128, G=4, Cg=16, K=3.

#define B_    4
#define C_    64
#define H_    128
#define W_    128
#define G_    4
#define CG_   16
#define HW_   (H_ * W_)          // 16384
#define NC8   2                  // channel octets per group (16/8)
#define NROWS 8                  // rows hb-1 .. hb+6 (2 out rows, d < 3.0)
#define WP    (W_ + 1)           // padded row (bank stagger)
#define TT    9                  // taps per channel
#define CS    (TT * HW_)         // out channel stride (elements)

__device__ __forceinline__ __half2 u2h(unsigned int u) {
    return *reinterpret_cast<__half2*>(&u);
}
__device__ __forceinline__ unsigned int h2u(__half2 h) {
    return *reinterpret_cast<unsigned int*>(&h);
}
__device__ __forceinline__ __half2 lerpu(__half2 w0, __half2 w1,
                                         unsigned int a, unsigned int b) {
    return __hfma2(w1, u2h(b), __hmul2(w0, u2h(a)));
}
__device__ __forceinline__ __half2 lerph(__half2 w0, __half2 w1,
                                         __half2 a, __half2 b) {
    return __hfma2(w1, b, __hmul2(w0, a));
}

// store 8 channels (4 half2) of one tap — streaming (evict-first)
__device__ __forceinline__ void st8(float* __restrict__ o, int tap,
                                    __half2 a, __half2 b, __half2 c, __half2 e)
{
    float* p = o + (size_t)tap * HW_;
    float2 f;
    f = __half22float2(a); __stcs(p,             f.x); __stcs(p + 1u * CS, f.y);
    f = __half22float2(b); __stcs(p + 2u * CS, f.x); __stcs(p + 3u * CS, f.y);
    f = __half22float2(c); __stcs(p + 4u * CS, f.x); __stcs(p + 5u * CS, f.y);
    f = __half22float2(e); __stcs(p + 6u * CS, f.x); __stcs(p + 7u * CS, f.y);
}

__global__ __launch_bounds__(256, 4)
void ddunfold_kernel(const float* __restrict__ x,
                     const float* __restrict__ dmap,
                     float* __restrict__ out)
{
    __shared__ uint4 tile[NC8][NROWS][WP];   // 33,024 B

    const int wo = threadIdx.x & (W_ - 1);   // 0..127
    const int ty = threadIdx.x >> 7;         // 0/1: which output row
    const int hb = blockIdx.x << 1;          // ho base (even)
    const int g  = blockIdx.y;               // 0..3
    const int b  = blockIdx.z;               // 0..3

    const int ho = hb + ty;
    const float d = dmap[((b * G_ + g) * H_ + ho) * W_ + wo];  // early load

    // ---- fused fill (vectorized): each thread fills 2 adjacent wo per iter.
    // 2 c8-planes x 8 rows x 64 wo-pairs = 1024 units / 256 thr = 4 iters.
    const float* __restrict__ xg = x + (size_t)(b * C_ + g * CG_) * HW_;
    #pragma unroll
    for (int i = 0; i < 4; i++) {
        const int u   = threadIdx.x + (i << 8);    // 0..1023
        const int wp2 = u & 63;                    // wo pair index
        const int rp  = u >> 6;                    // 0..15
        const int c8  = rp >> 3;                   // 0..1
        const int j   = rp & 7;                    // 0..7
        const int gr  = min(max(hb - 1 + j, 0), H_ - 1);
        const float2* xp = reinterpret_cast<const float2*>(
            xg + (size_t)(c8 * 8) * HW_ + gr * W_) + wp2;
        const float2 f0 = __ldg(xp);
        const float2 f1 = __ldg(xp + (HW_ / 2));
        const float2 f2 = __ldg(xp + 2 * (HW_ / 2));
        const float2 f3 = __ldg(xp + 3 * (HW_ / 2));
        const float2 f4 = __ldg(xp + 4 * (HW_ / 2));
        const float2 f5 = __ldg(xp + 5 * (HW_ / 2));
        const float2 f6 = __ldg(xp + 6 * (HW_ / 2));
        const float2 f7 = __ldg(xp + 7 * (HW_ / 2));

        uint4 va, vb;
        va.x = h2u(__floats2half2_rn(f0.x, f1.x));
        va.y = h2u(__floats2half2_rn(f2.x, f3.x));
        va.z = h2u(__floats2half2_rn(f4.x, f5.x));
        va.w = h2u(__floats2half2_rn(f6.x, f7.x));
        vb.x = h2u(__floats2half2_rn(f0.y, f1.y));
        vb.y = h2u(__floats2half2_rn(f2.y, f3.y));
        vb.z = h2u(__floats2half2_rn(f4.y, f5.y));
        vb.w = h2u(__floats2half2_rn(f6.y, f7.y));
        tile[c8][j][2 * wp2]     = va;
        tile[c8][j][2 * wp2 + 1] = vb;
    }

    // ---- k=0: exact integer tap at (ho-1, wo-1) ----
    const __half2 mh0 = __float2half2_rn(ho >= 1 ? 1.0f : 0.0f);
    const __half2 mw0 = __float2half2_rn(wo >= 1 ? 1.0f : 0.0f);
    const __half2 m00 = __hmul2(mh0, mw0);
    const int wm1 = max(wo - 1, 0);

    // ---- k=1,2: separable weights + smem indices ----
    __half2 ah0h[2], ah1h[2], bw0h[2], bw1h[2];
    int jh0[2], jh1[2], w0c[2], w1c[2];

    #pragma unroll
    for (int kk = 0; kk < 2; kk++) {
        const float kf = (float)(kk + 1);
        { // h axis
            const float p  = (float)(ho - 1) + kf * d;
            const float f0 = floorf(p);
            const float l  = p - f0;
            const bool  v0 = (f0 >= 0.0f)  && (f0 <= (float)(H_ - 1));
            const bool  v1 = (f0 >= -1.0f) && (f0 <= (float)(H_ - 2));
            ah0h[kk] = __float2half2_rn(v0 ? (1.0f - l) : 0.0f);
            ah1h[kk] = __float2half2_rn(v1 ? l : 0.0f);
            const int j = (int)f0 - (hb - 1);
            jh0[kk] = min(max(j,     0), NROWS - 1);
            jh1[kk] = min(max(j + 1, 0), NROWS - 1);
        }
        { // w axis
            const float p  = (float)(wo - 1) + kf * d;
            const float f0 = floorf(p);
            const float l  = p - f0;
            const bool  v0 = (f0 >= 0.0f)  && (f0 <= (float)(W_ - 1));
            const bool  v1 = (f0 >= -1.0f) && (f0 <= (float)(W_ - 2));
            bw0h[kk] = __float2half2_rn(v0 ? (1.0f - l) : 0.0f);
            bw1h[kk] = __float2half2_rn(v1 ? l : 0.0f);
            const int i0 = (int)f0;
            w0c[kk] = min(max(i0,     0), W_ - 1);
            w1c[kk] = min(max(i0 + 1, 0), W_ - 1);
        }
    }

    __syncthreads();

    const int pix = ho * W_ + wo;
    float* __restrict__ ob = out + ((size_t)(b * C_ + g * CG_)) * CS + pix;

    #pragma unroll
    for (int c8 = 0; c8 < NC8; c8++) {
        float* __restrict__ oc = ob + (size_t)(c8 * 8) * CS;

        // tap (0,0): direct copy with border mask
        {
            const uint4 q = tile[c8][ty][wm1];
            st8(oc, 0,
                __hmul2(m00, u2h(q.x)), __hmul2(m00, u2h(q.y)),
                __hmul2(m00, u2h(q.z)), __hmul2(m00, u2h(q.w)));
        }

        // taps (0,kw), kw=1,2: horizontal lerp on row ho-1 (mask mh0)
        #pragma unroll
        for (int kk = 0; kk < 2; kk++) {
            const uint4 q0 = tile[c8][ty][w0c[kk]];
            const uint4 q1 = tile[c8][ty][w1c[kk]];
            const __half2 wa = __hmul2(mh0, bw0h[kk]);
            const __half2 wb = __hmul2(mh0, bw1h[kk]);
            st8(oc, kk + 1,
                lerpu(wa, wb, q0.x, q1.x), lerpu(wa, wb, q0.y, q1.y),
                lerpu(wa, wb, q0.z, q1.z), lerpu(wa, wb, q0.w, q1.w));
        }

        // taps (kh,0), kh=1,2: vertical lerp on col wo-1 (mask mw0)
        #pragma unroll
        for (int kk = 0; kk < 2; kk++) {
            const uint4 q0 = tile[c8][jh0[kk]][wm1];
            const uint4 q1 = tile[c8][jh1[kk]][wm1];
            const __half2 wa = __hmul2(mw0, ah0h[kk]);
            const __half2 wb = __hmul2(mw0, ah1h[kk]);
            st8(oc, (kk + 1) * 3,
                lerpu(wa, wb, q0.x, q1.x), lerpu(wa, wb, q0.y, q1.y),
                lerpu(wa, wb, q0.z, q1.z), lerpu(wa, wb, q0.w, q1.w));
        }

        // full bilinear taps (kh,kw), kh,kw in {1,2}
        #pragma unroll
        for (int kh = 0; kh < 2; kh++) {
            const int r0 = jh0[kh];
            const int r1 = jh1[kh];
            #pragma unroll
            for (int kw = 0; kw < 2; kw++) {
                const uint4 q00 = tile[c8][r0][w0c[kw]];
                const uint4 q01 = tile[c8][r0][w1c[kw]];
                const uint4 q10 = tile[c8][r1][w0c[kw]];
                const uint4 q11 = tile[c8][r1][w1c[kw]];

                const __half2 ox = lerph(ah0h[kh], ah1h[kh],
                                         lerpu(bw0h[kw], bw1h[kw], q00.x, q01.x),
                                         lerpu(bw0h[kw], bw1h[kw], q10.x, q11.x));
                const __half2 oy = lerph(ah0h[kh], ah1h[kh],
                                         lerpu(bw0h[kw], bw1h[kw], q00.y, q01.y),
                                         lerpu(bw0h[kw], bw1h[kw], q10.y, q11.y));
                const __half2 oz = lerph(ah0h[kh], ah1h[kh],
                                         lerpu(bw0h[kw], bw1h[kw], q00.z, q01.z),
                                         lerpu(bw0h[kw], bw1h[kw], q10.z, q11.z));
                const __half2 ow = lerph(ah0h[kh], ah1h[kh],
                                         lerpu(bw0h[kw], bw1h[kw], q00.w, q01.w),
                                         lerpu(bw0h[kw], bw1h[kw], q10.w, q11.w));

                st8(oc, (kh + 1) * 3 + (kw + 1), ox, oy, oz, ow);
            }
        }
    }
}

extern "C" void kernel_launch(void* const* d_in, const int* in_sizes, int n_in,
                              void* d_out, int out_size)
{
    const float* x    = (const float*)d_in[0];
    const float* dmap = (const float*)d_in[1];
    float* out        = (float*)d_out;

    dim3 grid(H_ / 2, G_, B_);   // (ho pair, g, b)
    dim3 block(256);             // 2 rows x 128 wo
    ddunfold_kernel<<<grid, block>>>(x, dmap, out);
}

// round 13
// speedup vs baseline: 1.1007x; 1.0201x over previous
#include <cuda_runtime.h>
#include <cuda_fp16.h>

// DynamicDilationUnfold R13: R10 (best: 27.1us) + hoisted masked edge weights.
// 2-row tiles, 256 thr, 4 blocks/SM, 64 regs, scalar fused fill, uint4 smem
// packing, k=0 integer-tap specialization, streaming (__stcs) stores.
// B=4, C=64, H=W=128, G=4, Cg=16, K=3, pad=1, stride=1.

#define B_    4
#define C_    64
#define H_    128
#define W_    128
#define G_    4
#define CG_   16
#define HW_   (H_ * W_)          // 16384
#define NC8   2                  // channel octets per group (16/8)
#define NROWS 8                  // rows hb-1 .. hb+6 (2 out rows, d < 3.0)
#define WP    (W_ + 1)           // padded row (bank stagger)
#define TT    9                  // taps per channel
#define CS    (TT * HW_)         // out channel stride (elements)

__device__ __forceinline__ __half2 u2h(unsigned int u) {
    return *reinterpret_cast<__half2*>(&u);
}
__device__ __forceinline__ unsigned int h2u(__half2 h) {
    return *reinterpret_cast<unsigned int*>(&h);
}
__device__ __forceinline__ __half2 lerpu(__half2 w0, __half2 w1,
                                         unsigned int a, unsigned int b) {
    return __hfma2(w1, u2h(b), __hmul2(w0, u2h(a)));
}
__device__ __forceinline__ __half2 lerph(__half2 w0, __half2 w1,
                                         __half2 a, __half2 b) {
    return __hfma2(w1, b, __hmul2(w0, a));
}

// store 8 channels (4 half2) of one tap — streaming (evict-first)
__device__ __forceinline__ void st8(float* __restrict__ o, int tap,
                                    __half2 a, __half2 b, __half2 c, __half2 e)
{
    float* p = o + (size_t)tap * HW_;
    float2 f;
    f = __half22float2(a); __stcs(p,             f.x); __stcs(p + 1u * CS, f.y);
    f = __half22float2(b); __stcs(p + 2u * CS, f.x); __stcs(p + 3u * CS, f.y);
    f = __half22float2(c); __stcs(p + 4u * CS, f.x); __stcs(p + 5u * CS, f.y);
    f = __half22float2(e); __stcs(p + 6u * CS, f.x); __stcs(p + 7u * CS, f.y);
}

__global__ __launch_bounds__(256, 4)
void ddunfold_kernel(const float* __restrict__ x,
                     const float* __restrict__ dmap,
                     float* __restrict__ out)
{
    __shared__ uint4 tile[NC8][NROWS][WP];   // 33,024 B

    const int wo = threadIdx.x & (W_ - 1);   // 0..127
    const int ty = threadIdx.x >> 7;         // 0/1: which output row
    const int hb = blockIdx.x << 1;          // ho base (even)
    const int g  = blockIdx.y;               // 0..3
    const int b  = blockIdx.z;               // 0..3

    const int ho = hb + ty;
    const float d = dmap[((b * G_ + g) * H_ + ho) * W_ + wo];  // early load

    // ---- fused fill: fp32 planar -> half8 (uint4) packed smem rows ----
    const float* __restrict__ xg = x + (size_t)(b * C_ + g * CG_) * HW_;
    #pragma unroll
    for (int i = 0; i < 8; i++) {
        const int combo = 2 * i + ty;        // 0..15
        const int c8 = combo >> 3;           // 0..1
        const int j  = combo & 7;            // 0..7
        const int gr = min(max(hb - 1 + j, 0), H_ - 1);
        const float* xp = xg + (size_t)(c8 * 8) * HW_ + gr * W_ + wo;
        uint4 v;
        v.x = h2u(__floats2half2_rn(__ldg(xp),           __ldg(xp + HW_)));
        v.y = h2u(__floats2half2_rn(__ldg(xp + 2 * HW_), __ldg(xp + 3 * HW_)));
        v.z = h2u(__floats2half2_rn(__ldg(xp + 4 * HW_), __ldg(xp + 5 * HW_)));
        v.w = h2u(__floats2half2_rn(__ldg(xp + 6 * HW_), __ldg(xp + 7 * HW_)));
        tile[c8][j][wo] = v;
    }

    // ---- k=0: exact integer tap at (ho-1, wo-1) ----
    const __half2 mh0 = __float2half2_rn(ho >= 1 ? 1.0f : 0.0f);
    const __half2 mw0 = __float2half2_rn(wo >= 1 ? 1.0f : 0.0f);
    const __half2 m00 = __hmul2(mh0, mw0);
    const int wm1 = max(wo - 1, 0);

    // ---- k=1,2: separable weights + smem indices ----
    __half2 ah0h[2], ah1h[2], bw0h[2], bw1h[2];
    __half2 hw0m[2], hw1m[2], vw0m[2], vw1m[2];   // hoisted masked edge weights
    int jh0[2], jh1[2], w0c[2], w1c[2];

    #pragma unroll
    for (int kk = 0; kk < 2; kk++) {
        const float kf = (float)(kk + 1);
        { // h axis
            const float p  = (float)(ho - 1) + kf * d;
            const float f0 = floorf(p);
            const float l  = p - f0;
            const bool  v0 = (f0 >= 0.0f)  && (f0 <= (float)(H_ - 1));
            const bool  v1 = (f0 >= -1.0f) && (f0 <= (float)(H_ - 2));
            ah0h[kk] = __float2half2_rn(v0 ? (1.0f - l) : 0.0f);
            ah1h[kk] = __float2half2_rn(v1 ? l : 0.0f);
            const int j = (int)f0 - (hb - 1);
            jh0[kk] = min(max(j,     0), NROWS - 1);
            jh1[kk] = min(max(j + 1, 0), NROWS - 1);
        }
        { // w axis
            const float p  = (float)(wo - 1) + kf * d;
            const float f0 = floorf(p);
            const float l  = p - f0;
            const bool  v0 = (f0 >= 0.0f)  && (f0 <= (float)(W_ - 1));
            const bool  v1 = (f0 >= -1.0f) && (f0 <= (float)(W_ - 2));
            bw0h[kk] = __float2half2_rn(v0 ? (1.0f - l) : 0.0f);
            bw1h[kk] = __float2half2_rn(v1 ? l : 0.0f);
            const int i0 = (int)f0;
            w0c[kk] = min(max(i0,     0), W_ - 1);
            w1c[kk] = min(max(i0 + 1, 0), W_ - 1);
        }
        // masked weights for edge taps (row ho-1 / col wo-1), shared by both c8
        hw0m[kk] = __hmul2(mh0, bw0h[kk]);
        hw1m[kk] = __hmul2(mh0, bw1h[kk]);
        vw0m[kk] = __hmul2(mw0, ah0h[kk]);
        vw1m[kk] = __hmul2(mw0, ah1h[kk]);
    }

    __syncthreads();

    const int pix = ho * W_ + wo;
    float* __restrict__ ob = out + ((size_t)(b * C_ + g * CG_)) * CS + pix;

    #pragma unroll
    for (int c8 = 0; c8 < NC8; c8++) {
        float* __restrict__ oc = ob + (size_t)(c8 * 8) * CS;

        // tap (0,0): direct copy with border mask
        {
            const uint4 q = tile[c8][ty][wm1];
            st8(oc, 0,
                __hmul2(m00, u2h(q.x)), __hmul2(m00, u2h(q.y)),
                __hmul2(m00, u2h(q.z)), __hmul2(m00, u2h(q.w)));
        }

        // taps (0,kw), kw=1,2: horizontal lerp on row ho-1 (masked weights)
        #pragma unroll
        for (int kk = 0; kk < 2; kk++) {
            const uint4 q0 = tile[c8][ty][w0c[kk]];
            const uint4 q1 = tile[c8][ty][w1c[kk]];
            st8(oc, kk + 1,
                lerpu(hw0m[kk], hw1m[kk], q0.x, q1.x),
                lerpu(hw0m[kk], hw1m[kk], q0.y, q1.y),
                lerpu(hw0m[kk], hw1m[kk], q0.z, q1.z),
                lerpu(hw0m[kk], hw1m[kk], q0.w, q1.w));
        }

        // taps (kh,0), kh=1,2: vertical lerp on col wo-1 (masked weights)
        #pragma unroll
        for (int kk = 0; kk < 2; kk++) {
            const uint4 q0 = tile[c8][jh0[kk]][wm1];
            const uint4 q1 = tile[c8][jh1[kk]][wm1];
            st8(oc, (kk + 1) * 3,
                lerpu(vw0m[kk], vw1m[kk], q0.x, q1.x),
                lerpu(vw0m[kk], vw1m[kk], q0.y, q1.y),
                lerpu(vw0m[kk], vw1m[kk], q0.z, q1.z),
                lerpu(vw0m[kk], vw1m[kk], q0.w, q1.w));
        }

        // full bilinear taps (kh,kw), kh,kw in {1,2}
        #pragma unroll
        for (int kh = 0; kh < 2; kh++) {
            const int r0 = jh0[kh];
            const int r1 = jh1[kh];
            #pragma unroll
            for (int kw = 0; kw < 2; kw++) {
                const uint4 q00 = tile[c8][r0][w0c[kw]];
                const uint4 q01 = tile[c8][r0][w1c[kw]];
                const uint4 q10 = tile[c8][r1][w0c[kw]];
                const uint4 q11 = tile[c8][r1][w1c[kw]];

                const __half2 ox = lerph(ah0h[kh], ah1h[kh],
                                         lerpu(bw0h[kw], bw1h[kw], q00.x, q01.x),
                                         lerpu(bw0h[kw], bw1h[kw], q10.x, q11.x));
                const __half2 oy = lerph(ah0h[kh], ah1h[kh],
                                         lerpu(bw0h[kw], bw1h[kw], q00.y, q01.y),
                                         lerpu(bw0h[kw], bw1h[kw], q10.y, q11.y));
                const __half2 oz = lerph(ah0h[kh], ah1h[kh],
                                         lerpu(bw0h[kw], bw1h[kw], q00.z, q01.z),
                                         lerpu(bw0h[kw], bw1h[kw], q10.z, q11.z));
                const __half2 ow = lerph(ah0h[kh], ah1h[kh],
                                         lerpu(bw0h[kw], bw1h[kw], q00.w, q01.w),
                                         lerpu(bw0h[kw], bw1h[kw], q10.w, q11.w));

                st8(oc, (kh + 1) * 3 + (kw + 1), ox, oy, oz, ow);
            }
        }
    }
}

extern "C" void kernel_launch(void* const* d_in, const int* in_sizes, int n_in,
                              void* d_out, int out_size)
{
    const float* x    = (const float*)d_in[0];
    const float* dmap = (const float*)d_in[1];
    float* out        = (float*)d_out;

    dim3 grid(H_ / 2, G_, B_);   // (ho pair, g, b)
    dim3 block(256);             // 2 rows x 128 wo
    ddunfold_kernel<<<grid, block>>>(x, dmap, out);
}

// round 14
// speedup vs baseline: 1.1617x; 1.0555x over previous
#include <cuda_runtime.h>
#include <cuda_fp16.h>

// DynamicDilationUnfold R14 = R10 verbatim (measured best: 27.1us).
// 2-row tiles, 256 thr, 4 blocks/SM, 64 regs, scalar fused fill, uint4 smem
// packing (8 channels/LDS.128), k=0 integer-tap specialization, streaming
// (__stcs) output stores. B=4, C=64, H=W=128, G=4, Cg=16, K=3, pad=1, stride=1.
//
// Session notes (protect this shape):
//  - R9: launch_bounds(256,5) -> spills -> +6us. Keep 64 regs / 4 blocks.
//  - R11: 4-row tiles (512 thr) -> lost overlap -> +4us. Keep 2-row tiles.
//  - R12: float2 fill -> longer dep chains -> +2us. Keep scalar fill.
//  - R13: hoisted masked weights -> +1.5us. Keep weights in-loop.

#define B_    4
#define C_    64
#define H_    128
#define W_    128
#define G_    4
#define CG_   16
#define HW_   (H_ * W_)          // 16384
#define NC8   2                  // channel octets per group (16/8)
#define NROWS 8                  // rows hb-1 .. hb+6 (2 out rows, d < 3.0)
#define WP    (W_ + 1)           // padded row (bank stagger)
#define TT    9                  // taps per channel
#define CS    (TT * HW_)         // out channel stride (elements)

__device__ __forceinline__ __half2 u2h(unsigned int u) {
    return *reinterpret_cast<__half2*>(&u);
}
__device__ __forceinline__ unsigned int h2u(__half2 h) {
    return *reinterpret_cast<unsigned int*>(&h);
}
__device__ __forceinline__ __half2 lerpu(__half2 w0, __half2 w1,
                                         unsigned int a, unsigned int b) {
    return __hfma2(w1, u2h(b), __hmul2(w0, u2h(a)));
}
__device__ __forceinline__ __half2 lerph(__half2 w0, __half2 w1,
                                         __half2 a, __half2 b) {
    return __hfma2(w1, b, __hmul2(w0, a));
}

// store 8 channels (4 half2) of one tap — streaming (evict-first)
__device__ __forceinline__ void st8(float* __restrict__ o, int tap,
                                    __half2 a, __half2 b, __half2 c, __half2 e)
{
    float* p = o + (size_t)tap * HW_;
    float2 f;
    f = __half22float2(a); __stcs(p,             f.x); __stcs(p + 1u * CS, f.y);
    f = __half22float2(b); __stcs(p + 2u * CS, f.x); __stcs(p + 3u * CS, f.y);
    f = __half22float2(c); __stcs(p + 4u * CS, f.x); __stcs(p + 5u * CS, f.y);
    f = __half22float2(e); __stcs(p + 6u * CS, f.x); __stcs(p + 7u * CS, f.y);
}

__global__ __launch_bounds__(256, 4)
void ddunfold_kernel(const float* __restrict__ x,
                     const float* __restrict__ dmap,
                     float* __restrict__ out)
{
    __shared__ uint4 tile[NC8][NROWS][WP];   // 33,024 B

    const int wo = threadIdx.x & (W_ - 1);   // 0..127
    const int ty = threadIdx.x >> 7;         // 0/1: which output row
    const int hb = blockIdx.x << 1;          // ho base (even)
    const int g  = blockIdx.y;               // 0..3
    const int b  = blockIdx.z;               // 0..3

    const int ho = hb + ty;
    const float d = dmap[((b * G_ + g) * H_ + ho) * W_ + wo];  // early load

    // ---- fused fill: fp32 planar -> half8 (uint4) packed smem rows ----
    const float* __restrict__ xg = x + (size_t)(b * C_ + g * CG_) * HW_;
    #pragma unroll
    for (int i = 0; i < 8; i++) {
        const int combo = 2 * i + ty;        // 0..15
        const int c8 = combo >> 3;           // 0..1
        const int j  = combo & 7;            // 0..7
        const int gr = min(max(hb - 1 + j, 0), H_ - 1);
        const float* xp = xg + (size_t)(c8 * 8) * HW_ + gr * W_ + wo;
        uint4 v;
        v.x = h2u(__floats2half2_rn(__ldg(xp),           __ldg(xp + HW_)));
        v.y = h2u(__floats2half2_rn(__ldg(xp + 2 * HW_), __ldg(xp + 3 * HW_)));
        v.z = h2u(__floats2half2_rn(__ldg(xp + 4 * HW_), __ldg(xp + 5 * HW_)));
        v.w = h2u(__floats2half2_rn(__ldg(xp + 6 * HW_), __ldg(xp + 7 * HW_)));
        tile[c8][j][wo] = v;
    }

    // ---- k=0: exact integer tap at (ho-1, wo-1) ----
    const __half2 mh0 = __float2half2_rn(ho >= 1 ? 1.0f : 0.0f);
    const __half2 mw0 = __float2half2_rn(wo >= 1 ? 1.0f : 0.0f);
    const __half2 m00 = __hmul2(mh0, mw0);
    const int wm1 = max(wo - 1, 0);

    // ---- k=1,2: separable weights + smem indices ----
    __half2 ah0h[2], ah1h[2], bw0h[2], bw1h[2];
    int jh0[2], jh1[2], w0c[2], w1c[2];

    #pragma unroll
    for (int kk = 0; kk < 2; kk++) {
        const float kf = (float)(kk + 1);
        { // h axis
            const float p  = (float)(ho - 1) + kf * d;
            const float f0 = floorf(p);
            const float l  = p - f0;
            const bool  v0 = (f0 >= 0.0f)  && (f0 <= (float)(H_ - 1));
            const bool  v1 = (f0 >= -1.0f) && (f0 <= (float)(H_ - 2));
            ah0h[kk] = __float2half2_rn(v0 ? (1.0f - l) : 0.0f);
            ah1h[kk] = __float2half2_rn(v1 ? l : 0.0f);
            const int j = (int)f0 - (hb - 1);
            jh0[kk] = min(max(j,     0), NROWS - 1);
            jh1[kk] = min(max(j + 1, 0), NROWS - 1);
        }
        { // w axis
            const float p  = (float)(wo - 1) + kf * d;
            const float f0 = floorf(p);
            const float l  = p - f0;
            const bool  v0 = (f0 >= 0.0f)  && (f0 <= (float)(W_ - 1));
            const bool  v1 = (f0 >= -1.0f) && (f0 <= (float)(W_ - 2));
            bw0h[kk] = __float2half2_rn(v0 ? (1.0f - l) : 0.0f);
            bw1h[kk] = __float2half2_rn(v1 ? l : 0.0f);
            const int i0 = (int)f0;
            w0c[kk] = min(max(i0,     0), W_ - 1);
            w1c[kk] = min(max(i0 + 1, 0), W_ - 1);
        }
    }

    __syncthreads();

    const int pix = ho * W_ + wo;
    float* __restrict__ ob = out + ((size_t)(b * C_ + g * CG_)) * CS + pix;

    #pragma unroll
    for (int c8 = 0; c8 < NC8; c8++) {
        float* __restrict__ oc = ob + (size_t)(c8 * 8) * CS;

        // tap (0,0): direct copy with border mask
        {
            const uint4 q = tile[c8][ty][wm1];
            st8(oc, 0,
                __hmul2(m00, u2h(q.x)), __hmul2(m00, u2h(q.y)),
                __hmul2(m00, u2h(q.z)), __hmul2(m00, u2h(q.w)));
        }

        // taps (0,kw), kw=1,2: horizontal lerp on row ho-1 (mask mh0)
        #pragma unroll
        for (int kk = 0; kk < 2; kk++) {
            const uint4 q0 = tile[c8][ty][w0c[kk]];
            const uint4 q1 = tile[c8][ty][w1c[kk]];
            const __half2 wa = __hmul2(mh0, bw0h[kk]);
            const __half2 wb = __hmul2(mh0, bw1h[kk]);
            st8(oc, kk + 1,
                lerpu(wa, wb, q0.x, q1.x), lerpu(wa, wb, q0.y, q1.y),
                lerpu(wa, wb, q0.z, q1.z), lerpu(wa, wb, q0.w, q1.w));
        }

        // taps (kh,0), kh=1,2: vertical lerp on col wo-1 (mask mw0)
        #pragma unroll
        for (int kk = 0; kk < 2; kk++) {
            const uint4 q0 = tile[c8][jh0[kk]][wm1];
            const uint4 q1 = tile[c8][jh1[kk]][wm1];
            const __half2 wa = __hmul2(mw0, ah0h[kk]);
            const __half2 wb = __hmul2(mw0, ah1h[kk]);
            st8(oc, (kk + 1) * 3,
                lerpu(wa, wb, q0.x, q1.x), lerpu(wa, wb, q0.y, q1.y),
                lerpu(wa, wb, q0.z, q1.z), lerpu(wa, wb, q0.w, q1.w));
        }

        // full bilinear taps (kh,kw), kh,kw in {1,2}
        #pragma unroll
        for (int kh = 0; kh < 2; kh++) {
            const int r0 = jh0[kh];
            const int r1 = jh1[kh];
            #pragma unroll
            for (int kw = 0; kw < 2; kw++) {
                const uint4 q00 = tile[c8][r0][w0c[kw]];
                const uint4 q01 = tile[c8][r0][w1c[kw]];
                const uint4 q10 = tile[c8][r1][w0c[kw]];
                const uint4 q11 = tile[c8][r1][w1c[kw]];

                const __half2 ox = lerph(ah0h[kh], ah1h[kh],
                                         lerpu(bw0h[kw], bw1h[kw], q00.x, q01.x),
                                         lerpu(bw0h[kw], bw1h[kw], q10.x, q11.x));
                const __half2 oy = lerph(ah0h[kh], ah1h[kh],
                                         lerpu(bw0h[kw], bw1h[kw], q00.y, q01.y),
                                         lerpu(bw0h[kw], bw1h[kw], q10.y, q11.y));
                const __half2 oz = lerph(ah0h[kh], ah1h[kh],
                                         lerpu(bw0h[kw], bw1h[kw], q00.z, q01.z),
                                         lerpu(bw0h[kw], bw1h[kw], q10.z, q11.z));
                const __half2 ow = lerph(ah0h[kh], ah1h[kh],
                                         lerpu(bw0h[kw], bw1h[kw], q00.w, q01.w),
                                         lerpu(bw0h[kw], bw1h[kw], q10.w, q11.w));

                st8(oc, (kh + 1) * 3 + (kw + 1), ox, oy, oz, ow);
            }
        }
    }
}

extern "C" void kernel_launch(void* const* d_in, const int* in_sizes, int n_in,
                              void* d_out, int out_size)
{
    const float* x    = (const float*)d_in[0];
    const float* dmap = (const float*)d_in[1];
    float* out        = (float*)d_out;

    dim3 grid(H_ / 2, G_, B_);   // (ho pair, g, b)
    dim3 block(256);             // 2 rows x 128 wo
    ddunfold_kernel<<<grid, block>>>(x, dmap, out);
}